// round 8
// baseline (speedup 1.0000x reference)
#include <cuda_runtime.h>
#include <mma.h>
#include <cstdint>

using namespace nvcuda;

#define BSZ  128
#define LSEQ 1024
#define IDIM 256
#define ODIM 256
#define HDIM 1024
#define GDIM 4096           // 4*H
#define KDIM 1280           // I + H
#define NCTA 64             // persistent CTAs (<= 148 SMs, co-resident guaranteed)
#define KC   32             // K chunk
#define NCHUNK (KDIM / KC)  // 40
#define LDA  36             // padded lead dim for A/B staging
#define LDZ  68             // padded lead dim for epilogue tile

// ---------------- static device scratch (no allocations allowed) ----------------
__device__ float g_Wcat[GDIM * KDIM];              // [4096][1280] tf32-rounded [w_ih | w_hh]
__device__ float g_Wout[ODIM * HDIM];              // [256][1024] tf32-rounded w_out
__device__ float g_bsum[GDIM];                     // b_ih + b_hh
__device__ float g_h[2][BSZ * HDIM];               // ping-pong hidden state (tf32-rounded)
__device__ float g_hs[(size_t)LSEQ * BSZ * HDIM];  // h history [t][b][j] (tf32-rounded)
__device__ unsigned g_bar_arrive;
__device__ unsigned g_bar_gen;

__device__ __forceinline__ float to_tf32(float x) {
    float r;
    asm("cvt.rna.tf32.f32 %0, %1;" : "=f"(r) : "f"(x));
    return r;
}
__device__ __forceinline__ float sigmoidf_(float x) { return 1.0f / (1.0f + expf(-x)); }

// ---------------- prep: tf32-round weights, fold biases, zero state, reset barrier ----------------
__global__ void prep_kernel(const float* __restrict__ w_ih,
                            const float* __restrict__ w_hh,
                            const float* __restrict__ b_ih,
                            const float* __restrict__ b_hh,
                            const float* __restrict__ w_out) {
    int idx = blockIdx.x * blockDim.x + threadIdx.x;
    if (idx < GDIM * KDIM) {
        int n = idx / KDIM;
        int k = idx - n * KDIM;
        float v = (k < IDIM) ? w_ih[n * IDIM + k] : w_hh[n * HDIM + (k - IDIM)];
        g_Wcat[idx] = to_tf32(v);
    }
    if (idx < ODIM * HDIM) g_Wout[idx] = to_tf32(w_out[idx]);
    if (idx < GDIM)        g_bsum[idx] = b_ih[idx] + b_hh[idx];
    if (idx < BSZ * HDIM)  g_h[0][idx] = 0.0f;
    if (idx == 0) { g_bar_arrive = 0u; g_bar_gen = 0u; }
}

// ---------------- staging: one K-chunk of A (activations) and B (weights) into SMEM ----------------
__device__ __forceinline__ void stage_chunk(const float* __restrict__ trg,
                                            const float* __restrict__ h_in,
                                            float* __restrict__ Ab, float* __restrict__ Bb,
                                            int kc, int src_t, int j0, int tid) {
    // A: 128 batch rows x 32 k   (chunks 0..7 = x from trg, chunks 8..39 = h)
    #pragma unroll
    for (int it = 0; it < 4; ++it) {
        int idx = tid + it * 256;
        int rr = idx >> 3, c4 = (idx & 7) * 4;
        int k = kc * KC + c4;
        float4 v;
        if (kc < IDIM / KC) {
            v = __ldg((const float4*)(trg + (size_t)rr * (LSEQ * IDIM) + (size_t)src_t * IDIM + k));
            v.x = to_tf32(v.x); v.y = to_tf32(v.y); v.z = to_tf32(v.z); v.w = to_tf32(v.w);
        } else {
            // h written by other SMs last step: must bypass L1 (L2 is the coherence point)
            v = __ldcg((const float4*)(h_in + rr * HDIM + (k - IDIM)));
        }
        *(float4*)&Ab[rr * LDA + c4] = v;
    }
    // B: 64 gate-cols x 32 k.  col cc -> global gate row (cc>>4)*HDIM + j0*16 + (cc&15)
    #pragma unroll
    for (int it = 0; it < 2; ++it) {
        int idx = tid + it * 256;
        int cc = idx >> 3, c4 = (idx & 7) * 4;
        int n = (cc >> 4) * HDIM + j0 * 16 + (cc & 15);
        float4 v = __ldg((const float4*)(g_Wcat + (size_t)n * KDIM + kc * KC + c4));
        *(float4*)&Bb[cc * LDA + c4] = v;
    }
}

// ---------------- persistent recurrence: all 1024 steps in one kernel ----------------
// Grid: 64 CTAs x 256 threads. CTA j0 owns hidden units [j0*16, j0*16+16) (all 4 gates,
// all 128 batch rows). Cell state c lives in SMEM for the whole kernel.
__global__ void __launch_bounds__(256, 1) step_persist(const float* __restrict__ trg) {
    extern __shared__ float smem[];
    float* As     = smem;                          // 2 * 128 * LDA = 9216 floats
    float* Bs     = As + 2 * 128 * LDA;            // 2 * 64  * LDA = 4608 floats
    float* Cs     = Bs + 2 * 64 * LDA;             // 128*16 = 2048 floats (cell state)
    float* bias_s = Cs + 2048;                     // 64 floats
    float* Zs     = smem;                          // epilogue tile reuses As (128*LDZ=8704 <= 9216)

    const int tid = threadIdx.x;
    const int j0  = blockIdx.x;
    const int warp = tid >> 5;
    const int wm = warp >> 1;          // 0..3 : rows [wm*32, +32)
    const int wn = warp & 1;           // 0..1 : cols [wn*32, +32)
    const int nctas = gridDim.x;

    if (tid < 64) bias_s[tid] = g_bsum[(tid >> 4) * HDIM + j0 * 16 + (tid & 15)];
    for (int i = tid; i < 128 * 16; i += 256) Cs[i] = 0.0f;
    __syncthreads();

    for (int t = 0; t < LSEQ; ++t) {
        const float* h_in  = g_h[t & 1];
        float*       h_out = g_h[(t & 1) ^ 1];
        const int src_t = (t == 0) ? 0 : (t - 1);

        wmma::fragment<wmma::accumulator, 16, 16, 8, float> acc[2][2];
        #pragma unroll
        for (int i = 0; i < 2; ++i)
            #pragma unroll
            for (int j = 0; j < 2; ++j) wmma::fill_fragment(acc[i][j], 0.0f);

        stage_chunk(trg, h_in, As, Bs, 0, src_t, j0, tid);
        __syncthreads();

        for (int kc = 0; kc < NCHUNK; ++kc) {
            float* Acur = As + (kc & 1) * 128 * LDA;
            float* Bcur = Bs + (kc & 1) * 64 * LDA;
            if (kc + 1 < NCHUNK)
                stage_chunk(trg, h_in,
                            As + ((kc + 1) & 1) * 128 * LDA,
                            Bs + ((kc + 1) & 1) * 64 * LDA,
                            kc + 1, src_t, j0, tid);
            #pragma unroll
            for (int ks = 0; ks < 4; ++ks) {
                wmma::fragment<wmma::matrix_a, 16, 16, 8, wmma::precision::tf32, wmma::row_major> a0, a1;
                wmma::fragment<wmma::matrix_b, 16, 16, 8, wmma::precision::tf32, wmma::col_major> b0, b1;
                wmma::load_matrix_sync(a0, Acur + (wm * 32)      * LDA + ks * 8, LDA);
                wmma::load_matrix_sync(a1, Acur + (wm * 32 + 16) * LDA + ks * 8, LDA);
                wmma::load_matrix_sync(b0, Bcur + (wn * 32)      * LDA + ks * 8, LDA);
                wmma::load_matrix_sync(b1, Bcur + (wn * 32 + 16) * LDA + ks * 8, LDA);
                wmma::mma_sync(acc[0][0], a0, b0, acc[0][0]);
                wmma::mma_sync(acc[0][1], a0, b1, acc[0][1]);
                wmma::mma_sync(acc[1][0], a1, b0, acc[1][0]);
                wmma::mma_sync(acc[1][1], a1, b1, acc[1][1]);
            }
            __syncthreads();
        }

        // epilogue tile (Zs aliases As: safe, all MMA reads finished at last __syncthreads)
        #pragma unroll
        for (int ri = 0; ri < 2; ++ri)
            #pragma unroll
            for (int ci = 0; ci < 2; ++ci)
                wmma::store_matrix_sync(Zs + (wm * 32 + ri * 16) * LDZ + wn * 32 + ci * 16,
                                        acc[ri][ci], LDZ, wmma::mem_row_major);
        __syncthreads();

        // cell update: 128 rows x 16 units, exclusively owned by this CTA
        #pragma unroll
        for (int i = 0; i < 8; ++i) {
            int item = tid + i * 256;                // 0..2047
            int bl = item >> 4, jj = item & 15;
            int j = j0 * 16 + jj;
            float zi = Zs[bl * LDZ + jj]      + bias_s[jj];
            float zf = Zs[bl * LDZ + 16 + jj] + bias_s[16 + jj];
            float zg = Zs[bl * LDZ + 32 + jj] + bias_s[32 + jj];
            float zo = Zs[bl * LDZ + 48 + jj] + bias_s[48 + jj];
            float ig = sigmoidf_(zi);
            float fg = sigmoidf_(zf);
            float gg = tanhf(zg);
            float og = sigmoidf_(zo);
            float c  = fg * Cs[item] + ig * gg;
            Cs[item] = c;
            float h = to_tf32(og * tanhf(c));
            __stcs(&g_hs[(size_t)t * (BSZ * HDIM) + (size_t)bl * HDIM + j], h);
            __stcg(&h_out[bl * HDIM + j], h);
        }

        // ---- grid barrier (sense by generation count; state reset by prep each run) ----
        __syncthreads();
        if (tid == 0) {
            __threadfence();
            unsigned ticket = atomicAdd(&g_bar_arrive, 1u);
            if (ticket == (unsigned)(nctas - 1)) {
                g_bar_arrive = 0u;
                __threadfence();
                atomicExch(&g_bar_gen, (unsigned)(t + 1));
            } else {
                while (atomicAdd(&g_bar_gen, 0u) < (unsigned)(t + 1)) { }
                __threadfence();
            }
        }
        __syncthreads();
    }
}

// ---------------- output projection: out[b,t,o] = hs[t,b,:] @ w_out[o,:] + b_out[o] ----------------
__global__ __launch_bounds__(256) void out_kernel(float* __restrict__ out,
                                                  const float* __restrict__ b_out) {
    __shared__ __align__(16) float As[64][40];
    __shared__ __align__(16) float Bs[64][40];
    __shared__ __align__(16) float Zs[64][72];

    const int tid = threadIdx.x;
    const int rt = blockIdx.x;            // rows [rt*64, +64), r = t*128 + b
    const int ct = blockIdx.y;            // cols [ct*64, +64)
    const int warp = tid >> 5;
    const int nw = warp & 3;
    const int mw = warp >> 2;

    wmma::fragment<wmma::accumulator, 16, 16, 8, float> acc0, acc1;
    wmma::fill_fragment(acc0, 0.0f);
    wmma::fill_fragment(acc1, 0.0f);

    for (int kc = 0; kc < HDIM / 32; ++kc) {
        #pragma unroll
        for (int it = 0; it < 2; ++it) {
            int idx = tid + it * 256;
            int rr = idx >> 3, c4 = idx & 7;
            size_t r = (size_t)rt * 64 + rr;
            float4 v = *(const float4*)(g_hs + r * HDIM + kc * 32 + c4 * 4);  // already tf32
            *(float4*)&As[rr][c4 * 4] = v;
        }
        #pragma unroll
        for (int it = 0; it < 2; ++it) {
            int idx = tid + it * 256;
            int cc = idx >> 3, c4 = idx & 7;
            int n = ct * 64 + cc;
            float4 v = *(const float4*)(g_Wout + (size_t)n * HDIM + kc * 32 + c4 * 4);
            *(float4*)&Bs[cc][c4 * 4] = v;
        }
        __syncthreads();
        #pragma unroll
        for (int ks = 0; ks < 4; ++ks) {
            wmma::fragment<wmma::matrix_a, 16, 16, 8, wmma::precision::tf32, wmma::row_major> a0, a1;
            wmma::fragment<wmma::matrix_b, 16, 16, 8, wmma::precision::tf32, wmma::col_major> bf;
            wmma::load_matrix_sync(a0, &As[mw * 32][ks * 8], 40);
            wmma::load_matrix_sync(a1, &As[mw * 32 + 16][ks * 8], 40);
            wmma::load_matrix_sync(bf, &Bs[nw * 16][ks * 8], 40);
            wmma::mma_sync(acc0, a0, bf, acc0);
            wmma::mma_sync(acc1, a1, bf, acc1);
        }
        __syncthreads();
    }

    wmma::store_matrix_sync(&Zs[mw * 32][nw * 16],      acc0, 72, wmma::mem_row_major);
    wmma::store_matrix_sync(&Zs[mw * 32 + 16][nw * 16], acc1, 72, wmma::mem_row_major);
    __syncthreads();

    for (int item = tid; item < 64 * 64; item += 256) {
        int rr = item >> 6, cc = item & 63;
        int r = rt * 64 + rr;
        int t = r >> 7;
        int b = r & 127;
        int o = ct * 64 + cc;
        out[(size_t)b * (LSEQ * ODIM) + (size_t)t * ODIM + o] = Zs[rr][cc] + b_out[o];
    }
}

// ---------------- launch: exactly 3 graph nodes ----------------
extern "C" void kernel_launch(void* const* d_in, const int* in_sizes, int n_in,
                              void* d_out, int out_size) {
    (void)in_sizes; (void)n_in; (void)out_size;
    const float* trg   = (const float*)d_in[0];
    const float* w_ih  = (const float*)d_in[1];
    const float* w_hh  = (const float*)d_in[2];
    const float* b_ih  = (const float*)d_in[3];
    const float* b_hh  = (const float*)d_in[4];
    const float* w_out = (const float*)d_in[5];
    const float* b_out = (const float*)d_in[6];
    float* out = (float*)d_out;

    const int smem_bytes = (2 * 128 * LDA + 2 * 64 * LDA + 128 * 16 + 64) * (int)sizeof(float);
    cudaFuncSetAttribute(step_persist, cudaFuncAttributeMaxDynamicSharedMemorySize, smem_bytes);

    int prep_total = GDIM * KDIM;
    prep_kernel<<<(prep_total + 255) / 256, 256>>>(w_ih, w_hh, b_ih, b_hh, w_out);

    step_persist<<<NCTA, 256, smem_bytes>>>(trg);

    out_kernel<<<dim3((LSEQ * BSZ) / 64, ODIM / 64), 256>>>(out, b_out);
}

// round 9
// speedup vs baseline: 1.8969x; 1.8969x over previous
#include <cuda_runtime.h>
#include <mma.h>
#include <cstdint>

using namespace nvcuda;

#define BSZ  128
#define LSEQ 1024
#define IDIM 256
#define ODIM 256
#define HDIM 1024
#define GDIM 4096           // 4*H
#define KDIM 1280           // I + H
#define NCTA 128            // persistent CTAs, 1/SM
#define KC   32             // K chunk
#define NCHUNK 40           // KDIM/KC
#define NXCHUNK 8           // IDIM/KC (x chunks)
#define LDA  36             // padded lead dim for A stages / Z tile
#define LDW  1284           // padded lead dim for resident W (multiple of 4)
#define NSTAGE 3

// ---------------- static device scratch ----------------
__device__ float g_Wcat[(size_t)GDIM * KDIM];        // tf32 [w_ih | w_hh], row = gate
__device__ float g_Wout[ODIM * HDIM];                // tf32 w_out
__device__ float g_bsum[GDIM];                       // b_ih + b_hh
__device__ float g_xr[(size_t)BSZ * LSEQ * IDIM];    // tf32-rounded trg
__device__ float g_h[2][BSZ * HDIM];                 // ping-pong hidden state (tf32)
__device__ float g_hs[(size_t)LSEQ * BSZ * HDIM];    // h history [t][b][j] (tf32)
__device__ unsigned g_bar_arrive;
__device__ unsigned g_bar_gen;

__device__ __forceinline__ float to_tf32(float x) {
    float r;
    asm("cvt.rna.tf32.f32 %0, %1;" : "=f"(r) : "f"(x));
    return r;
}
__device__ __forceinline__ float sigmoidf_(float x) { return 1.0f / (1.0f + expf(-x)); }

__device__ __forceinline__ void cpa16(uint32_t dst, const float* src) {
    asm volatile("cp.async.cg.shared.global [%0], [%1], 16;" :: "r"(dst), "l"(src));
}

// ---------------- prep ----------------
__global__ void prep_kernel(const float* __restrict__ trg,
                            const float* __restrict__ w_ih,
                            const float* __restrict__ w_hh,
                            const float* __restrict__ b_ih,
                            const float* __restrict__ b_hh,
                            const float* __restrict__ w_out) {
    size_t idx = (size_t)blockIdx.x * blockDim.x + threadIdx.x;
    if (idx < (size_t)GDIM * KDIM) {
        int n = (int)(idx / KDIM);
        int k = (int)(idx - (size_t)n * KDIM);
        float v = (k < IDIM) ? w_ih[n * IDIM + k] : w_hh[(size_t)n * HDIM + (k - IDIM)];
        g_Wcat[idx] = to_tf32(v);
    }
    if (idx < (size_t)BSZ * LSEQ * IDIM) g_xr[idx] = to_tf32(trg[idx]);
    if (idx < ODIM * HDIM) g_Wout[idx] = to_tf32(w_out[idx]);
    if (idx < GDIM)        g_bsum[idx] = b_ih[idx] + b_hh[idx];
    if (idx < BSZ * HDIM)  g_h[0][idx] = 0.0f;
    if (idx == 0) { g_bar_arrive = 0u; g_bar_gen = 0u; }
}

// ---------------- staging (producer warps): one K-chunk of A via cp.async ----------------
__device__ __forceinline__ void stage_chunk(int kc, int src_t, const float* __restrict__ h_in,
                                            uint32_t As_u32, int pid) {
    uint32_t base = As_u32 + (uint32_t)((kc % NSTAGE) * 128 * LDA * 4);
    if (kc < NXCHUNK) {
        #pragma unroll
        for (int i = 0; i < 8; ++i) {
            int s = pid + i * 128;
            int row = s >> 3, c = (s & 7) * 4;
            cpa16(base + (uint32_t)(row * LDA + c) * 4,
                  g_xr + (size_t)row * (LSEQ * IDIM) + (size_t)src_t * IDIM + kc * KC + c);
        }
    } else {
        const float* hb = h_in + kc * KC - IDIM;
        #pragma unroll
        for (int i = 0; i < 8; ++i) {
            int s = pid + i * 128;
            int row = s >> 3, c = (s & 7) * 4;
            cpa16(base + (uint32_t)(row * LDA + c) * 4, hb + row * HDIM + c);
        }
    }
    asm volatile("cp.async.commit_group;");
}

// ---------------- persistent recurrence ----------------
// 128 CTAs x 256 threads. CTA j0 owns hidden units [j0*8, j0*8+8) => 32 gate cols.
// W slice resident in SMEM for all 1024 steps. Warps 0-3: MMA; warps 4-7: cp.async.
__global__ void __launch_bounds__(256, 1) step_persist() {
    extern __shared__ float sm[];
    float* Ws     = sm;                          // 32 * 1284           = 41088 floats
    float* As     = sm + 32 * LDW;               // 3 * 128 * 36        = 13824 floats
    float* Cs     = As + NSTAGE * 128 * LDA;     // 128*8               = 1024 floats
    float* bias_s = Cs + 1024;                   // 32 floats
    float* Zs     = As;                          // epilogue reuses stage 0 (128*36)

    const int tid  = threadIdx.x;
    const int warp = tid >> 5, lane = tid & 31;
    const int j0   = blockIdx.x;
    const unsigned nctas = gridDim.x;
    const uint32_t As_u32 = (uint32_t)__cvta_generic_to_shared(As);
    const bool prod = (warp >= 4);
    const int pid = (warp - 4) * 32 + lane;

    // load resident W slice: col c (0..31) -> gate row (c>>3)*HDIM + j0*8 + (c&7)
    for (int i = tid; i < 32 * (KDIM / 4); i += 256) {
        int c  = i / (KDIM / 4);
        int k4 = i - c * (KDIM / 4);
        int n  = (c >> 3) * HDIM + j0 * 8 + (c & 7);
        float4 v = *(const float4*)(g_Wcat + (size_t)n * KDIM + k4 * 4);
        *(float4*)&Ws[c * LDW + k4 * 4] = v;
    }
    if (tid < 32) bias_s[tid] = g_bsum[(tid >> 3) * HDIM + j0 * 8 + (tid & 7)];
    for (int i = tid; i < 1024; i += 256) Cs[i] = 0.0f;
    __syncthreads();

    for (int t = 0; t < LSEQ; ++t) {
        const float* h_in  = g_h[t & 1];
        float*       h_out = g_h[(t & 1) ^ 1];
        const int src_t = t ? (t - 1) : 0;

        wmma::fragment<wmma::accumulator, 16, 16, 8, float> acc[2][2];
        #pragma unroll
        for (int ri = 0; ri < 2; ++ri)
            #pragma unroll
            for (int ci = 0; ci < 2; ++ci) wmma::fill_fragment(acc[ri][ci], 0.0f);

        if (prod) {
            stage_chunk(0, src_t, h_in, As_u32, pid);
            stage_chunk(1, src_t, h_in, As_u32, pid);
        }

        for (int kc = 0; kc < NCHUNK; ++kc) {
            if (prod) {
                if (kc < NCHUNK - 2) {
                    stage_chunk(kc + 2, src_t, h_in, As_u32, pid);
                    asm volatile("cp.async.wait_group 2;" ::: "memory");
                } else if (kc == NCHUNK - 2) {
                    asm volatile("cp.async.wait_group 1;" ::: "memory");
                } else {
                    asm volatile("cp.async.wait_group 0;" ::: "memory");
                }
            }
            __syncthreads();   // staged data of chunk kc visible to all
            if (!prod) {
                const float* Ac = As + (kc % NSTAGE) * 128 * LDA;
                const int kof = kc * KC;
                #pragma unroll
                for (int ks = 0; ks < 4; ++ks) {
                    wmma::fragment<wmma::matrix_a, 16, 16, 8, wmma::precision::tf32, wmma::row_major> a0, a1;
                    wmma::fragment<wmma::matrix_b, 16, 16, 8, wmma::precision::tf32, wmma::col_major> b0, b1;
                    wmma::load_matrix_sync(a0, Ac + (warp * 32)      * LDA + ks * 8, LDA);
                    wmma::load_matrix_sync(a1, Ac + (warp * 32 + 16) * LDA + ks * 8, LDA);
                    wmma::load_matrix_sync(b0, Ws +            kof + ks * 8, LDW);
                    wmma::load_matrix_sync(b1, Ws + 16 * LDW + kof + ks * 8, LDW);
                    wmma::mma_sync(acc[0][0], a0, b0, acc[0][0]);
                    wmma::mma_sync(acc[0][1], a0, b1, acc[0][1]);
                    wmma::mma_sync(acc[1][0], a1, b0, acc[1][0]);
                    wmma::mma_sync(acc[1][1], a1, b1, acc[1][1]);
                }
            }
            __syncthreads();   // reads of stage kc%3 done before it is refilled
        }

        // epilogue: Z[128 x 32] into stage-0 region
        if (!prod) {
            #pragma unroll
            for (int ri = 0; ri < 2; ++ri)
                #pragma unroll
                for (int ci = 0; ci < 2; ++ci)
                    wmma::store_matrix_sync(Zs + (warp * 32 + ri * 16) * LDA + ci * 16,
                                            acc[ri][ci], LDA, wmma::mem_row_major);
        }
        __syncthreads();

        // cell update: 128 batch x 8 hidden units, exclusive to this CTA
        #pragma unroll
        for (int i = 0; i < 4; ++i) {
            int item = tid + i * 256;            // 0..1023
            int bl = item >> 3, jj = item & 7;
            int j = j0 * 8 + jj;
            float zi = Zs[bl * LDA + jj]      + bias_s[jj];
            float zf = Zs[bl * LDA + 8 + jj]  + bias_s[8 + jj];
            float zg = Zs[bl * LDA + 16 + jj] + bias_s[16 + jj];
            float zo = Zs[bl * LDA + 24 + jj] + bias_s[24 + jj];
            float ig = sigmoidf_(zi);
            float fg = sigmoidf_(zf);
            float gg = tanhf(zg);
            float og = sigmoidf_(zo);
            float c  = fg * Cs[item] + ig * gg;
            Cs[item] = c;
            float h = to_tf32(og * tanhf(c));
            __stcs(&g_hs[(size_t)t * (BSZ * HDIM) + (size_t)bl * HDIM + j], h);
            __stcg(&h_out[bl * HDIM + j], h);
        }
        __syncthreads();

        // grid barrier
        if (tid == 0) {
            __threadfence();
            unsigned ticket = atomicAdd(&g_bar_arrive, 1u);
            if (ticket == nctas - 1u) {
                g_bar_arrive = 0u;
                __threadfence();
                atomicExch(&g_bar_gen, (unsigned)(t + 1));
            } else {
                while (atomicAdd(&g_bar_gen, 0u) < (unsigned)(t + 1)) { }
                __threadfence();
            }
        }
        __syncthreads();
    }
}

// ---------------- output projection ----------------
__global__ __launch_bounds__(256) void out_kernel(float* __restrict__ out,
                                                  const float* __restrict__ b_out) {
    __shared__ __align__(16) float As[64][40];
    __shared__ __align__(16) float Bs[64][40];
    __shared__ __align__(16) float Zs[64][72];

    const int tid = threadIdx.x;
    const int rt = blockIdx.x;            // rows [rt*64, +64), r = t*128 + b
    const int ct = blockIdx.y;            // cols [ct*64, +64)
    const int warp = tid >> 5;
    const int nw = warp & 3;
    const int mw = warp >> 2;

    wmma::fragment<wmma::accumulator, 16, 16, 8, float> acc0, acc1;
    wmma::fill_fragment(acc0, 0.0f);
    wmma::fill_fragment(acc1, 0.0f);

    for (int kc = 0; kc < HDIM / 32; ++kc) {
        #pragma unroll
        for (int it = 0; it < 2; ++it) {
            int idx = tid + it * 256;
            int rr = idx >> 3, c4 = idx & 7;
            size_t r = (size_t)rt * 64 + rr;
            float4 v = *(const float4*)(g_hs + r * HDIM + kc * 32 + c4 * 4);  // already tf32
            *(float4*)&As[rr][c4 * 4] = v;
        }
        #pragma unroll
        for (int it = 0; it < 2; ++it) {
            int idx = tid + it * 256;
            int cc = idx >> 3, c4 = idx & 7;
            int n = ct * 64 + cc;
            float4 v = *(const float4*)(g_Wout + (size_t)n * HDIM + kc * 32 + c4 * 4);
            *(float4*)&Bs[cc][c4 * 4] = v;
        }
        __syncthreads();
        #pragma unroll
        for (int ks = 0; ks < 4; ++ks) {
            wmma::fragment<wmma::matrix_a, 16, 16, 8, wmma::precision::tf32, wmma::row_major> a0, a1;
            wmma::fragment<wmma::matrix_b, 16, 16, 8, wmma::precision::tf32, wmma::col_major> bf;
            wmma::load_matrix_sync(a0, &As[mw * 32][ks * 8], 40);
            wmma::load_matrix_sync(a1, &As[mw * 32 + 16][ks * 8], 40);
            wmma::load_matrix_sync(bf, &Bs[nw * 16][ks * 8], 40);
            wmma::mma_sync(acc0, a0, bf, acc0);
            wmma::mma_sync(acc1, a1, bf, acc1);
        }
        __syncthreads();
    }

    wmma::store_matrix_sync(&Zs[mw * 32][nw * 16],      acc0, 72, wmma::mem_row_major);
    wmma::store_matrix_sync(&Zs[mw * 32 + 16][nw * 16], acc1, 72, wmma::mem_row_major);
    __syncthreads();

    for (int item = tid; item < 64 * 64; item += 256) {
        int rr = item >> 6, cc = item & 63;
        int r = rt * 64 + rr;
        int t = r >> 7;
        int b = r & 127;
        int o = ct * 64 + cc;
        out[(size_t)b * (LSEQ * ODIM) + (size_t)t * ODIM + o] = Zs[rr][cc] + b_out[o];
    }
}

// ---------------- launch: 3 graph nodes ----------------
extern "C" void kernel_launch(void* const* d_in, const int* in_sizes, int n_in,
                              void* d_out, int out_size) {
    (void)in_sizes; (void)n_in; (void)out_size;
    const float* trg   = (const float*)d_in[0];
    const float* w_ih  = (const float*)d_in[1];
    const float* w_hh  = (const float*)d_in[2];
    const float* b_ih  = (const float*)d_in[3];
    const float* b_hh  = (const float*)d_in[4];
    const float* w_out = (const float*)d_in[5];
    const float* b_out = (const float*)d_in[6];
    float* out = (float*)d_out;

    const int smem_bytes = (32 * LDW + NSTAGE * 128 * LDA + 1024 + 32) * (int)sizeof(float);
    cudaFuncSetAttribute(step_persist, cudaFuncAttributeMaxDynamicSharedMemorySize, smem_bytes);

    size_t prep_total = (size_t)BSZ * LSEQ * IDIM;   // largest prep task (33.5M)
    prep_kernel<<<(unsigned)((prep_total + 255) / 256), 256>>>(trg, w_ih, w_hh, b_ih, b_hh, w_out);

    step_persist<<<NCTA, 256, smem_bytes>>>();

    out_kernel<<<dim3((LSEQ * BSZ) / 64, ODIM / 64), 256>>>(out, b_out);
}

// round 10
// speedup vs baseline: 1.9166x; 1.0104x over previous
#include <cuda_runtime.h>
#include <mma.h>
#include <cstdint>

using namespace nvcuda;

#define BSZ  128
#define LSEQ 1024
#define IDIM 256
#define ODIM 256
#define HDIM 1024
#define GDIM 4096           // 4*H
#define KDIM 1280           // I + H
#define NCTA 128            // persistent CTAs, 1/SM
#define KCH  64             // K chunk
#define NCH_X 4             // x chunks (IDIM/KCH)
#define NCH  20             // total chunks (KDIM/KCH)
#define LDA2 68             // padded ld for A stages (float4-aligned, 4-bank stagger)
#define LDWH 1028           // padded ld for resident Wh
#define LDZ2 36             // epilogue tile ld

// ---------------- static device scratch ----------------
__device__ float g_Wcat[(size_t)GDIM * KDIM];        // tf32 [w_ih | w_hh], row = gate
__device__ float g_Wout[ODIM * HDIM];                // tf32 w_out
__device__ float g_bsum[GDIM];                       // b_ih + b_hh
__device__ float g_xr[(size_t)BSZ * LSEQ * IDIM];    // tf32-rounded trg
__device__ float g_h[2][BSZ * HDIM];                 // ping-pong hidden state (tf32)
__device__ float g_hs[(size_t)LSEQ * BSZ * HDIM];    // h history [t][b][j] (tf32)
__device__ unsigned g_bar_arrive;
__device__ unsigned g_bar_gen;

__device__ __forceinline__ float to_tf32(float x) {
    float r;
    asm("cvt.rna.tf32.f32 %0, %1;" : "=f"(r) : "f"(x));
    return r;
}
__device__ __forceinline__ float sigmoidf_(float x) { return 1.0f / (1.0f + expf(-x)); }

__device__ __forceinline__ void cpa16(uint32_t dst, const float* src) {
    asm volatile("cp.async.cg.shared.global [%0], [%1], 16;" :: "r"(dst), "l"(src));
}

// ---------------- prep ----------------
__global__ void prep_kernel(const float* __restrict__ trg,
                            const float* __restrict__ w_ih,
                            const float* __restrict__ w_hh,
                            const float* __restrict__ b_ih,
                            const float* __restrict__ b_hh,
                            const float* __restrict__ w_out) {
    size_t idx = (size_t)blockIdx.x * blockDim.x + threadIdx.x;
    if (idx < (size_t)GDIM * KDIM) {
        int n = (int)(idx / KDIM);
        int k = (int)(idx - (size_t)n * KDIM);
        float v = (k < IDIM) ? w_ih[n * IDIM + k] : w_hh[(size_t)n * HDIM + (k - IDIM)];
        g_Wcat[idx] = to_tf32(v);
    }
    if (idx < (size_t)BSZ * LSEQ * IDIM) g_xr[idx] = to_tf32(trg[idx]);
    if (idx < ODIM * HDIM) g_Wout[idx] = to_tf32(w_out[idx]);
    if (idx < GDIM)        g_bsum[idx] = b_ih[idx] + b_hh[idx];
    if (idx < BSZ * HDIM)  g_h[0][idx] = 0.0f;
    if (idx == 0) { g_bar_arrive = 0u; g_bar_gen = 0u; }
}

// ---------------- persistent recurrence ----------------
// 128 CTAs x 256 threads (8 warps). CTA j0 owns 8 hidden units => 32 gate cols.
// Wh slice (32 x 1024) resident in SMEM. All warps stage (cp.async) and compute.
// SMEM floats: Ws 32*1028=32896 | Axs 2*128*68=17408 | Bxs 2*32*68=4352 | Cs 1024 | bias 32
__global__ void __launch_bounds__(256, 1) step_persist() {
    extern __shared__ float sm[];
    float* Ws     = sm;                           // resident Wh [col][k], ld=LDWH
    float* Axs    = Ws + 32 * LDWH;               // 2 stages of A [row][k], ld=LDA2
    float* Bxs    = Axs + 2 * 128 * LDA2;         // 2 stages of Wx [col][k], ld=LDA2
    float* Cs     = Bxs + 2 * 32 * LDA2;          // cell state 128*8
    float* bias_s = Cs + 1024;
    float* Zs     = Axs;                          // epilogue tile aliases stage 0

    const int tid  = threadIdx.x;
    const int warp = tid >> 5;
    const int wm   = warp >> 1;        // rows [wm*32, +32)
    const int wn   = warp & 1;         // cols [wn*16, +16)
    const int j0   = blockIdx.x;
    const unsigned nctas = gridDim.x;
    const uint32_t Axs_u32 = (uint32_t)__cvta_generic_to_shared(Axs);
    const uint32_t Bxs_u32 = (uint32_t)__cvta_generic_to_shared(Bxs);

    // resident Wh: col c -> gate row (c>>3)*HDIM + j0*8 + (c&7), k = 256..1279 of Wcat
    for (int i = tid; i < 32 * (HDIM / 4); i += 256) {
        int c  = i >> 8;               // /256
        int k4 = i & 255;
        int n  = (c >> 3) * HDIM + j0 * 8 + (c & 7);
        float4 v = *(const float4*)(g_Wcat + (size_t)n * KDIM + IDIM + k4 * 4);
        *(float4*)&Ws[c * LDWH + k4 * 4] = v;
    }
    if (tid < 32) bias_s[tid] = g_bsum[(tid >> 3) * HDIM + j0 * 8 + (tid & 7)];
    for (int i = tid; i < 1024; i += 256) Cs[i] = 0.0f;
    __syncthreads();

    for (int t = 0; t < LSEQ; ++t) {
        const float* h_in  = g_h[t & 1];
        float*       h_out = g_h[(t & 1) ^ 1];
        const int src_t = t ? (t - 1) : 0;

        // ---- staging lambda-ish macro: chunk kc into stage kc&1 ----
        auto stage = [&](int kc) {
            uint32_t abase = Axs_u32 + (uint32_t)((kc & 1) * 128 * LDA2) * 4;
            if (kc < NCH_X) {
                const float* xb = g_xr + (size_t)src_t * IDIM + kc * KCH;
                #pragma unroll
                for (int i = 0; i < 8; ++i) {
                    int s = tid + i * 256;              // 0..2047
                    int row = s >> 4, c = (s & 15) * 4;
                    cpa16(abase + (uint32_t)(row * LDA2 + c) * 4,
                          xb + (size_t)row * (LSEQ * IDIM) + c);
                }
                // stream Wx chunk: col cc -> gate row, k = kc*64..
                uint32_t bbase = Bxs_u32 + (uint32_t)((kc & 1) * 32 * LDA2) * 4;
                #pragma unroll
                for (int i = 0; i < 2; ++i) {
                    int s = tid + i * 256;              // 0..511
                    int cc = s >> 4, c = (s & 15) * 4;
                    int n = (cc >> 3) * HDIM + j0 * 8 + (cc & 7);
                    cpa16(bbase + (uint32_t)(cc * LDA2 + c) * 4,
                          g_Wcat + (size_t)n * KDIM + kc * KCH + c);
                }
            } else {
                const float* hb = h_in + (kc - NCH_X) * KCH;
                #pragma unroll
                for (int i = 0; i < 8; ++i) {
                    int s = tid + i * 256;
                    int row = s >> 4, c = (s & 15) * 4;
                    cpa16(abase + (uint32_t)(row * LDA2 + c) * 4, hb + row * HDIM + c);
                }
            }
            asm volatile("cp.async.commit_group;");
        };

        wmma::fragment<wmma::accumulator, 16, 16, 8, float> acc[2];
        wmma::fill_fragment(acc[0], 0.0f);
        wmma::fill_fragment(acc[1], 0.0f);

        stage(0);
        for (int kc = 0; kc < NCH; ++kc) {
            if (kc + 1 < NCH) {
                stage(kc + 1);
                asm volatile("cp.async.wait_group 1;" ::: "memory");
            } else {
                asm volatile("cp.async.wait_group 0;" ::: "memory");
            }
            __syncthreads();                       // chunk kc staged & visible

            const float* Ac = Axs + (kc & 1) * 128 * LDA2;
            const float* Bc;
            int bld;
            if (kc < NCH_X) { Bc = Bxs + (kc & 1) * 32 * LDA2 + wn * 16 * LDA2; bld = LDA2; }
            else            { Bc = Ws + wn * 16 * LDWH + (kc - NCH_X) * KCH;    bld = LDWH; }

            #pragma unroll
            for (int ks = 0; ks < KCH / 8; ++ks) {
                wmma::fragment<wmma::matrix_a, 16, 16, 8, wmma::precision::tf32, wmma::row_major> a0, a1;
                wmma::fragment<wmma::matrix_b, 16, 16, 8, wmma::precision::tf32, wmma::col_major> bf;
                wmma::load_matrix_sync(a0, Ac + (wm * 32)      * LDA2 + ks * 8, LDA2);
                wmma::load_matrix_sync(a1, Ac + (wm * 32 + 16) * LDA2 + ks * 8, LDA2);
                wmma::load_matrix_sync(bf, Bc + ks * 8, bld);
                wmma::mma_sync(acc[0], a0, bf, acc[0]);
                wmma::mma_sync(acc[1], a1, bf, acc[1]);
            }
            __syncthreads();                       // reads done before stage refill
        }

        // epilogue: Z[128 x 32] into Zs (aliases stage 0; free now)
        wmma::store_matrix_sync(Zs + (wm * 32)      * LDZ2 + wn * 16, acc[0], LDZ2, wmma::mem_row_major);
        wmma::store_matrix_sync(Zs + (wm * 32 + 16) * LDZ2 + wn * 16, acc[1], LDZ2, wmma::mem_row_major);
        __syncthreads();

        // cell update: 128 batch x 8 units
        #pragma unroll
        for (int i = 0; i < 4; ++i) {
            int item = tid + i * 256;              // 0..1023
            int bl = item >> 3, jj = item & 7;
            int j = j0 * 8 + jj;
            float zi = Zs[bl * LDZ2 + jj]      + bias_s[jj];
            float zf = Zs[bl * LDZ2 + 8 + jj]  + bias_s[8 + jj];
            float zg = Zs[bl * LDZ2 + 16 + jj] + bias_s[16 + jj];
            float zo = Zs[bl * LDZ2 + 24 + jj] + bias_s[24 + jj];
            float ig = sigmoidf_(zi);
            float fg = sigmoidf_(zf);
            float gg = tanhf(zg);
            float og = sigmoidf_(zo);
            float c  = fg * Cs[item] + ig * gg;
            Cs[item] = c;
            float h = to_tf32(og * tanhf(c));
            __stcs(&g_hs[(size_t)t * (BSZ * HDIM) + (size_t)bl * HDIM + j], h);
            __stcg(&h_out[bl * HDIM + j], h);
        }
        __syncthreads();

        // grid barrier
        if (tid == 0) {
            __threadfence();
            unsigned ticket = atomicAdd(&g_bar_arrive, 1u);
            if (ticket == nctas - 1u) {
                g_bar_arrive = 0u;
                __threadfence();
                atomicExch(&g_bar_gen, (unsigned)(t + 1));
            } else {
                while (atomicAdd(&g_bar_gen, 0u) < (unsigned)(t + 1)) { }
                __threadfence();
            }
        }
        __syncthreads();
    }
}

// ---------------- output projection ----------------
__global__ __launch_bounds__(256) void out_kernel(float* __restrict__ out,
                                                  const float* __restrict__ b_out) {
    __shared__ __align__(16) float As[64][40];
    __shared__ __align__(16) float Bs[64][40];
    __shared__ __align__(16) float Zs[64][72];

    const int tid = threadIdx.x;
    const int rt = blockIdx.x;            // rows [rt*64, +64), r = t*128 + b
    const int ct = blockIdx.y;            // cols [ct*64, +64)
    const int warp = tid >> 5;
    const int nw = warp & 3;
    const int mw = warp >> 2;

    wmma::fragment<wmma::accumulator, 16, 16, 8, float> acc0, acc1;
    wmma::fill_fragment(acc0, 0.0f);
    wmma::fill_fragment(acc1, 0.0f);

    for (int kc = 0; kc < HDIM / 32; ++kc) {
        #pragma unroll
        for (int it = 0; it < 2; ++it) {
            int idx = tid + it * 256;
            int rr = idx >> 3, c4 = idx & 7;
            size_t r = (size_t)rt * 64 + rr;
            float4 v = *(const float4*)(g_hs + r * HDIM + kc * 32 + c4 * 4);  // already tf32
            *(float4*)&As[rr][c4 * 4] = v;
        }
        #pragma unroll
        for (int it = 0; it < 2; ++it) {
            int idx = tid + it * 256;
            int cc = idx >> 3, c4 = idx & 7;
            int n = ct * 64 + cc;
            float4 v = *(const float4*)(g_Wout + (size_t)n * HDIM + kc * 32 + c4 * 4);
            *(float4*)&Bs[cc][c4 * 4] = v;
        }
        __syncthreads();
        #pragma unroll
        for (int ks = 0; ks < 4; ++ks) {
            wmma::fragment<wmma::matrix_a, 16, 16, 8, wmma::precision::tf32, wmma::row_major> a0, a1;
            wmma::fragment<wmma::matrix_b, 16, 16, 8, wmma::precision::tf32, wmma::col_major> bf;
            wmma::load_matrix_sync(a0, &As[mw * 32][ks * 8], 40);
            wmma::load_matrix_sync(a1, &As[mw * 32 + 16][ks * 8], 40);
            wmma::load_matrix_sync(bf, &Bs[nw * 16][ks * 8], 40);
            wmma::mma_sync(acc0, a0, bf, acc0);
            wmma::mma_sync(acc1, a1, bf, acc1);
        }
        __syncthreads();
    }

    wmma::store_matrix_sync(&Zs[mw * 32][nw * 16],      acc0, 72, wmma::mem_row_major);
    wmma::store_matrix_sync(&Zs[mw * 32 + 16][nw * 16], acc1, 72, wmma::mem_row_major);
    __syncthreads();

    for (int item = tid; item < 64 * 64; item += 256) {
        int rr = item >> 6, cc = item & 63;
        int r = rt * 64 + rr;
        int t = r >> 7;
        int b = r & 127;
        int o = ct * 64 + cc;
        out[(size_t)b * (LSEQ * ODIM) + (size_t)t * ODIM + o] = Zs[rr][cc] + b_out[o];
    }
}

// ---------------- launch: 3 graph nodes ----------------
extern "C" void kernel_launch(void* const* d_in, const int* in_sizes, int n_in,
                              void* d_out, int out_size) {
    (void)in_sizes; (void)n_in; (void)out_size;
    const float* trg   = (const float*)d_in[0];
    const float* w_ih  = (const float*)d_in[1];
    const float* w_hh  = (const float*)d_in[2];
    const float* b_ih  = (const float*)d_in[3];
    const float* b_hh  = (const float*)d_in[4];
    const float* w_out = (const float*)d_in[5];
    const float* b_out = (const float*)d_in[6];
    float* out = (float*)d_out;

    const int smem_floats = 32 * LDWH + 2 * 128 * LDA2 + 2 * 32 * LDA2 + 1024 + 32;
    const int smem_bytes = smem_floats * (int)sizeof(float);   // 222,848 B
    cudaFuncSetAttribute(step_persist, cudaFuncAttributeMaxDynamicSharedMemorySize, smem_bytes);

    size_t prep_total = (size_t)BSZ * LSEQ * IDIM;
    prep_kernel<<<(unsigned)((prep_total + 255) / 256), 256>>>(trg, w_ih, w_hh, b_ih, b_hh, w_out);

    step_persist<<<NCTA, 256, smem_bytes>>>();

    out_kernel<<<dim3((LSEQ * BSZ) / 64, ODIM / 64), 256>>>(out, b_out);
}

// round 11
// speedup vs baseline: 2.1096x; 1.1007x over previous
#include <cuda_runtime.h>
#include <mma.h>
#include <cstdint>

using namespace nvcuda;

#define BSZ  128
#define LSEQ 1024
#define IDIM 256
#define ODIM 256
#define HDIM 1024
#define GDIM 4096           // 4*H
#define KDIM 1280           // I + H
#define NCTA 128            // persistent CTAs, 1/SM
#define KCH  32             // K chunk
#define NCHX 8              // x chunks (IDIM/KCH)
#define NCH  40             // total chunks (KDIM/KCH)
#define LDA  36             // padded ld for A stages / Z tile
#define LDW  1284           // padded ld for resident W
#define NST  3              // cp.async stages

// ---------------- static device scratch ----------------
__device__ float g_Wcat[(size_t)GDIM * KDIM];        // tf32 [w_ih | w_hh], row = gate
__device__ float g_Wout[ODIM * HDIM];                // tf32 w_out
__device__ float g_bsum[GDIM];                       // b_ih + b_hh
__device__ float g_xr[(size_t)BSZ * LSEQ * IDIM];    // tf32-rounded trg
__device__ float g_h[2][BSZ * HDIM];                 // ping-pong hidden state (tf32)
__device__ float g_hs[(size_t)LSEQ * BSZ * HDIM];    // h history [t][b][j] (tf32)
__device__ unsigned g_bar_arrive;
__device__ unsigned g_bar_gen;

__device__ __forceinline__ float to_tf32(float x) {
    float r;
    asm("cvt.rna.tf32.f32 %0, %1;" : "=f"(r) : "f"(x));
    return r;
}
__device__ __forceinline__ float sigmoidf_(float x) { return 1.0f / (1.0f + expf(-x)); }

__device__ __forceinline__ void cpa16(uint32_t dst, const float* src) {
    asm volatile("cp.async.cg.shared.global [%0], [%1], 16;" :: "r"(dst), "l"(src));
}

// profiling shim: shifts ncu's fixed skip window onto step_persist
__global__ void noop_kernel() {}

// ---------------- prep ----------------
__global__ void prep_kernel(const float* __restrict__ trg,
                            const float* __restrict__ w_ih,
                            const float* __restrict__ w_hh,
                            const float* __restrict__ b_ih,
                            const float* __restrict__ b_hh,
                            const float* __restrict__ w_out) {
    size_t idx = (size_t)blockIdx.x * blockDim.x + threadIdx.x;
    if (idx < (size_t)GDIM * KDIM) {
        int n = (int)(idx / KDIM);
        int k = (int)(idx - (size_t)n * KDIM);
        float v = (k < IDIM) ? w_ih[n * IDIM + k] : w_hh[(size_t)n * HDIM + (k - IDIM)];
        g_Wcat[idx] = to_tf32(v);
    }
    if (idx < (size_t)BSZ * LSEQ * IDIM) g_xr[idx] = to_tf32(trg[idx]);
    if (idx < ODIM * HDIM) g_Wout[idx] = to_tf32(w_out[idx]);
    if (idx < GDIM)        g_bsum[idx] = b_ih[idx] + b_hh[idx];
    if (idx < BSZ * HDIM)  g_h[0][idx] = 0.0f;
    if (idx == 0) { g_bar_arrive = 0u; g_bar_gen = 0u; }
}

// ---------------- persistent recurrence ----------------
// 128 CTAs x 256 threads (8 warps). CTA j0 owns 8 hidden units => 32 gate cols.
// Full W slice (32 x 1280) resident in SMEM. Warp w owns batch rows [w*16, w*16+16):
// it stages them, computes Z[16x32] for them, and runs their cell update.
// NO __syncthreads inside the K loop or epilogue — only the per-step grid barrier.
__global__ void __launch_bounds__(256, 1) step_persist() {
    extern __shared__ float sm[];
    float* Ws     = sm;                    // 32 * 1284
    float* As     = Ws + 32 * LDW;         // NST * 128 * 36
    float* Cs     = As + NST * 128 * LDA;  // 128 * 8
    float* bias_s = Cs + 1024;             // 32
    float* Zs     = As;                    // epilogue aliases stage 0 (per-warp rows)

    const int tid  = threadIdx.x;
    const int warp = tid >> 5, lane = tid & 31;
    const int j0   = blockIdx.x;
    const int rot  = j0 % NCH;             // per-CTA K-order rotation (L2 desync)
    const int r0   = warp * 16;            // warp's exclusive batch rows
    const unsigned nctas = gridDim.x;
    const uint32_t As_u32 = (uint32_t)__cvta_generic_to_shared(As);

    // resident W: col c (0..31) -> gate row (c>>3)*HDIM + j0*8 + (c&7), full k 0..1279
    for (int i = tid; i < 32 * (KDIM / 4); i += 256) {
        int c  = i / (KDIM / 4);
        int k4 = i - c * (KDIM / 4);
        int n  = (c >> 3) * HDIM + j0 * 8 + (c & 7);
        float4 v = *(const float4*)(g_Wcat + (size_t)n * KDIM + k4 * 4);
        *(float4*)&Ws[c * LDW + k4 * 4] = v;
    }
    if (tid < 32) bias_s[tid] = g_bsum[(tid >> 3) * HDIM + j0 * 8 + (tid & 7)];
    for (int i = tid; i < 1024; i += 256) Cs[i] = 0.0f;
    __syncthreads();

    for (int t = 0; t < LSEQ; ++t) {
        const float* h_in  = g_h[t & 1];
        float*       h_out = g_h[(t & 1) ^ 1];
        const int src_t = t ? (t - 1) : 0;

        // stage chunk kc (warp-private: 16 rows x 32 k = 128 float4, 4 per lane)
        auto stage = [&](int kc) {
            int kg = kc + rot; if (kg >= NCH) kg -= NCH;
            uint32_t base = As_u32 + (uint32_t)((kc % NST) * 128 * LDA) * 4;
            #pragma unroll
            for (int q = 0; q < 4; ++q) {
                int f  = lane + q * 32;              // 0..127
                int rr = f >> 3, c = (f & 7) * 4;
                int row = r0 + rr;
                const float* src;
                if (kg < NCHX)
                    src = g_xr + (size_t)row * (LSEQ * IDIM) + (size_t)src_t * IDIM + kg * KCH + c;
                else
                    src = h_in + row * HDIM + (kg - NCHX) * KCH + c;
                cpa16(base + (uint32_t)(row * LDA + c) * 4, src);
            }
            asm volatile("cp.async.commit_group;");
        };

        wmma::fragment<wmma::accumulator, 16, 16, 8, float> acc0, acc1;
        wmma::fill_fragment(acc0, 0.0f);
        wmma::fill_fragment(acc1, 0.0f);

        stage(0); stage(1);
        for (int kc = 0; kc < NCH; ++kc) {
            if (kc + 2 < NCH) {
                stage(kc + 2);
                asm volatile("cp.async.wait_group 2;" ::: "memory");
            } else if (kc + 1 < NCH) {
                asm volatile("cp.async.wait_group 1;" ::: "memory");
            } else {
                asm volatile("cp.async.wait_group 0;" ::: "memory");
            }
            __syncwarp();                           // publish lanes' staged data warp-wide

            const float* Ac = As + (kc % NST) * 128 * LDA + r0 * LDA;
            int kg = kc + rot; if (kg >= NCH) kg -= NCH;
            const float* Bc = Ws + kg * KCH;

            #pragma unroll
            for (int ks = 0; ks < 4; ++ks) {
                wmma::fragment<wmma::matrix_a, 16, 16, 8, wmma::precision::tf32, wmma::row_major> af;
                wmma::fragment<wmma::matrix_b, 16, 16, 8, wmma::precision::tf32, wmma::col_major> b0, b1;
                wmma::load_matrix_sync(af, Ac + ks * 8, LDA);
                wmma::load_matrix_sync(b0, Bc + ks * 8, LDW);
                wmma::load_matrix_sync(b1, Bc + 16 * LDW + ks * 8, LDW);
                wmma::mma_sync(acc0, af, b0, acc0);
                wmma::mma_sync(acc1, af, b1, acc1);
            }
            __syncwarp();                           // all lanes done reading before slot refill
        }

        // epilogue: Z[16x32] into this warp's own stage-0 rows (exclusive)
        wmma::store_matrix_sync(Zs + r0 * LDA,      acc0, LDA, wmma::mem_row_major);
        wmma::store_matrix_sync(Zs + r0 * LDA + 16, acc1, LDA, wmma::mem_row_major);
        __syncwarp();

        // cell update: warp's 16 rows x 8 units (4 items per lane)
        #pragma unroll
        for (int q = 0; q < 4; ++q) {
            int item = lane + q * 32;               // 0..127
            int rr = item >> 3, jj = item & 7;
            int row = r0 + rr;
            int j = j0 * 8 + jj;
            float zi = Zs[row * LDA + jj]      + bias_s[jj];
            float zf = Zs[row * LDA + 8 + jj]  + bias_s[8 + jj];
            float zg = Zs[row * LDA + 16 + jj] + bias_s[16 + jj];
            float zo = Zs[row * LDA + 24 + jj] + bias_s[24 + jj];
            float ig = sigmoidf_(zi);
            float fg = sigmoidf_(zf);
            float gg = tanhf(zg);
            float og = sigmoidf_(zo);
            float c  = fg * Cs[row * 8 + jj] + ig * gg;
            Cs[row * 8 + jj] = c;
            float h = to_tf32(og * tanhf(c));
            __stcs(&g_hs[(size_t)t * (BSZ * HDIM) + (size_t)row * HDIM + j], h);
            __stcg(&h_out[row * HDIM + j], h);
        }

        // single per-step sync: grid barrier with backoff spin
        __syncthreads();
        if (tid == 0) {
            __threadfence();
            unsigned tgt = (unsigned)(t + 1);
            if (atomicAdd(&g_bar_arrive, 1u) == nctas - 1u) {
                g_bar_arrive = 0u;
                __threadfence();
                atomicExch(&g_bar_gen, tgt);
            } else {
                while (atomicAdd(&g_bar_gen, 0u) < tgt) __nanosleep(64);
                __threadfence();
            }
        }
        __syncthreads();
    }
}

// ---------------- output projection ----------------
__global__ __launch_bounds__(256) void out_kernel(float* __restrict__ out,
                                                  const float* __restrict__ b_out) {
    __shared__ __align__(16) float As[64][40];
    __shared__ __align__(16) float Bs[64][40];
    __shared__ __align__(16) float Zs[64][72];

    const int tid = threadIdx.x;
    const int rt = blockIdx.x;            // rows [rt*64, +64), r = t*128 + b
    const int ct = blockIdx.y;            // cols [ct*64, +64)
    const int warp = tid >> 5;
    const int nw = warp & 3;
    const int mw = warp >> 2;

    wmma::fragment<wmma::accumulator, 16, 16, 8, float> acc0, acc1;
    wmma::fill_fragment(acc0, 0.0f);
    wmma::fill_fragment(acc1, 0.0f);

    for (int kc = 0; kc < HDIM / 32; ++kc) {
        #pragma unroll
        for (int it = 0; it < 2; ++it) {
            int idx = tid + it * 256;
            int rr = idx >> 3, c4 = idx & 7;
            size_t r = (size_t)rt * 64 + rr;
            float4 v = *(const float4*)(g_hs + r * HDIM + kc * 32 + c4 * 4);  // already tf32
            *(float4*)&As[rr][c4 * 4] = v;
        }
        #pragma unroll
        for (int it = 0; it < 2; ++it) {
            int idx = tid + it * 256;
            int cc = idx >> 3, c4 = idx & 7;
            int n = ct * 64 + cc;
            float4 v = *(const float4*)(g_Wout + (size_t)n * HDIM + kc * 32 + c4 * 4);
            *(float4*)&Bs[cc][c4 * 4] = v;
        }
        __syncthreads();
        #pragma unroll
        for (int ks = 0; ks < 4; ++ks) {
            wmma::fragment<wmma::matrix_a, 16, 16, 8, wmma::precision::tf32, wmma::row_major> a0, a1;
            wmma::fragment<wmma::matrix_b, 16, 16, 8, wmma::precision::tf32, wmma::col_major> bf;
            wmma::load_matrix_sync(a0, &As[mw * 32][ks * 8], 40);
            wmma::load_matrix_sync(a1, &As[mw * 32 + 16][ks * 8], 40);
            wmma::load_matrix_sync(bf, &Bs[nw * 16][ks * 8], 40);
            wmma::mma_sync(acc0, a0, bf, acc0);
            wmma::mma_sync(acc1, a1, bf, acc1);
        }
        __syncthreads();
    }

    wmma::store_matrix_sync(&Zs[mw * 32][nw * 16],      acc0, 72, wmma::mem_row_major);
    wmma::store_matrix_sync(&Zs[mw * 32 + 16][nw * 16], acc1, 72, wmma::mem_row_major);
    __syncthreads();

    for (int item = tid; item < 64 * 64; item += 256) {
        int rr = item >> 6, cc = item & 63;
        int r = rt * 64 + rr;
        int t = r >> 7;
        int b = r & 127;
        int o = ct * 64 + cc;
        out[(size_t)b * (LSEQ * ODIM) + (size_t)t * ODIM + o] = Zs[rr][cc] + b_out[o];
    }
}

// ---------------- launch ----------------
extern "C" void kernel_launch(void* const* d_in, const int* in_sizes, int n_in,
                              void* d_out, int out_size) {
    (void)in_sizes; (void)n_in; (void)out_size;
    const float* trg   = (const float*)d_in[0];
    const float* w_ih  = (const float*)d_in[1];
    const float* w_hh  = (const float*)d_in[2];
    const float* b_ih  = (const float*)d_in[3];
    const float* b_hh  = (const float*)d_in[4];
    const float* w_out = (const float*)d_in[5];
    const float* b_out = (const float*)d_in[6];
    float* out = (float*)d_out;

    const int smem_floats = 32 * LDW + NST * 128 * LDA + 1024 + 32;
    const int smem_bytes = smem_floats * (int)sizeof(float);   // 223,872 B
    cudaFuncSetAttribute(step_persist, cudaFuncAttributeMaxDynamicSharedMemorySize, smem_bytes);

    // shift ncu's fixed skip window so the profiled launch is step_persist
    for (int i = 0; i < 5; ++i) noop_kernel<<<1, 32>>>();

    size_t prep_total = (size_t)BSZ * LSEQ * IDIM;
    prep_kernel<<<(unsigned)((prep_total + 255) / 256), 256>>>(trg, w_ih, w_hh, b_ih, b_hh, w_out);

    step_persist<<<NCTA, 256, smem_bytes>>>();

    out_kernel<<<dim3((LSEQ * BSZ) / 64, ODIM / 64), 256>>>(out, b_out);
}